// round 2
// baseline (speedup 1.0000x reference)
#include <cuda_runtime.h>
#include <stdint.h>

// out[j] = (|bits[j % 4096]| > 0.5) ? 1.0f : 0.0f   for all j in [0, 48*1024*1024)
// Period in float4 units: 4096/4 = 1024. Since every float4 is 16B-aligned and
// 4*idx mod 4096 == 4*(idx & 1023), the pattern index is just (idx & 1023).

static constexpr int N_BITS   = 4096;
static constexpr int PAT4     = N_BITS / 4;       // 1024 float4s = 16 KB
static constexpr int THREADS  = 512;
static constexpr int BLOCKS   = 1184;             // 148 SMs * 8

__global__ __launch_bounds__(THREADS, 4)
void fill_periodic_kernel(const float* __restrict__ bits,
                          float4* __restrict__ out4,
                          long long n4)
{
    __shared__ float4 pat[PAT4];

    // Build the 16 KB pattern once per block (all loads L1/L2 hits after warmup).
    const float4* bits4 = reinterpret_cast<const float4*>(bits);
    for (int i = threadIdx.x; i < PAT4; i += THREADS) {
        float4 b = bits4[i];
        float4 v;
        v.x = (fabsf(b.x) > 0.5f) ? 1.0f : 0.0f;
        v.y = (fabsf(b.y) > 0.5f) ? 1.0f : 0.0f;
        v.z = (fabsf(b.z) > 0.5f) ? 1.0f : 0.0f;
        v.w = (fabsf(b.w) > 0.5f) ? 1.0f : 0.0f;
        pat[i] = v;
    }
    __syncthreads();

    long long idx    = (long long)blockIdx.x * THREADS + threadIdx.x;
    long long stride = (long long)gridDim.x * THREADS;

    // n4 = 12,582,912 is divisible by stride granularity only approximately;
    // grid-stride loop handles the tail. Unroll for store MLP.
    #pragma unroll 4
    for (; idx < n4; idx += stride) {
        out4[idx] = pat[idx & (PAT4 - 1)];
    }
}

extern "C" void kernel_launch(void* const* d_in, const int* in_sizes, int n_in,
                              void* d_out, int out_size)
{
    const float* bits = (const float*)d_in[0];
    float4* out4 = (float4*)d_out;
    long long n4 = (long long)out_size / 4;   // 50331648 / 4 = 12582912

    fill_periodic_kernel<<<BLOCKS, THREADS>>>(bits, out4, n4);
}

// round 3
// speedup vs baseline: 1.3088x; 1.3088x over previous
#include <cuda_runtime.h>
#include <stdint.h>

// out[j] = (|bits[j % 4096]| > 0.5) ? 1.0f : 0.0f  for all j in [0, 48*2^20).
// In float4 units the pattern period is 1024, and pattern index = idx & 1023.
// With grid stride a multiple of 1024 (float4 units), each thread's pattern
// index is INVARIANT across its grid-stride iterations -> hoist the value to
// a register and run a pure STG.128 store loop (no smem, no LDS).

static constexpr int THREADS = 512;
static constexpr int BLOCKS  = 592;   // 148 SMs * 4 resident blocks; one wave
// stride = 592*512 = 303104 = 296*1024  -> multiple of 1024  ✓

__global__ __launch_bounds__(THREADS, 4)
void fill_periodic_kernel(const float* __restrict__ bits,
                          float4* __restrict__ out4,
                          long long n4)
{
    long long idx    = (long long)blockIdx.x * THREADS + threadIdx.x;
    const long long stride = (long long)gridDim.x * THREADS;

    // Pattern value for this thread — constant for the whole loop.
    const float4* bits4 = reinterpret_cast<const float4*>(bits);
    float4 b = __ldg(&bits4[idx & 1023]);   // 16 KB total; L1/L2 hits
    float4 v;
    v.x = (fabsf(b.x) > 0.5f) ? 1.0f : 0.0f;
    v.y = (fabsf(b.y) > 0.5f) ? 1.0f : 0.0f;
    v.z = (fabsf(b.z) > 0.5f) ? 1.0f : 0.0f;
    v.w = (fabsf(b.w) > 0.5f) ? 1.0f : 0.0f;

    // Pure streaming-store loop. Unroll for outstanding-store MLP.
    #pragma unroll 4
    for (; idx < n4; idx += stride) {
        __stcs(&out4[idx], v);
    }
}

extern "C" void kernel_launch(void* const* d_in, const int* in_sizes, int n_in,
                              void* d_out, int out_size)
{
    const float* bits = (const float*)d_in[0];
    float4* out4 = (float4*)d_out;
    long long n4 = (long long)out_size / 4;   // 50331648 / 4 = 12582912

    fill_periodic_kernel<<<BLOCKS, THREADS>>>(bits, out4, n4);
}